// round 1
// baseline (speedup 1.0000x reference)
#include <cuda_runtime.h>
#include <cuda_bf16.h>
#include <math.h>

// ---------------- scratch (no allocation allowed; use __device__ globals) ----
#define B 4096
#define LATENT 512
#define H 8
#define D 64
#define KVB_N (H * (2 * D + 1))   // 1032

__device__ float g_h[B * LATENT];      // post-GEMM1 / post-LN
__device__ float g_h2[B * LATENT];     // post-GEMM2
__device__ float g_kvb[B * KVB_N];     // post-GEMM3

// ---------------- GEMM: C[M,N] = A[M,K] @ Bmat[K,N] + bias ------------------
// CONCAT: A is concat([A0 (M,512), A1 (M,512)]) along K (K=1024)
#define BM 64
#define BN 64
#define BK 16

template <bool CONCAT>
__global__ __launch_bounds__(256) void gemm_bias_kernel(
    const float* __restrict__ A0, const float* __restrict__ A1,
    const float* __restrict__ Bmat, const float* __restrict__ bias,
    float* __restrict__ C, int M, int N, int K)
{
    __shared__ float As[BK][BM];
    __shared__ float Bs[BK][BN];

    int t  = threadIdx.x;
    int tx = t & 15;          // 0..15 (N direction)
    int ty = t >> 4;          // 0..15 (M direction)
    int row0 = blockIdx.y * BM + ty * 4;
    int col0 = blockIdx.x * BN + tx * 4;

    // A-tile load mapping: 64 rows x 4 float4 (along K)
    int am  = t >> 2;          // 0..63
    int ak4 = (t & 3) * 4;     // 0,4,8,12
    // B-tile load mapping: 16 rows x 16 float4 (along N)
    int bk  = t >> 4;          // 0..15
    int bn4 = (t & 15) * 4;

    float acc[4][4] = {};

    for (int k0 = 0; k0 < K; k0 += BK) {
        // ---- load A tile (transpose into As[k][m]) ----
        {
            int gm = blockIdx.y * BM + am;
            int gk = k0 + ak4;
            const float* ap;
            if (CONCAT) {
                ap = (gk < 512) ? (A0 + (size_t)gm * 512 + gk)
                                : (A1 + (size_t)gm * 512 + (gk - 512));
            } else {
                ap = A0 + (size_t)gm * K + gk;
            }
            float4 av = *(const float4*)ap;
            As[ak4 + 0][am] = av.x;
            As[ak4 + 1][am] = av.y;
            As[ak4 + 2][am] = av.z;
            As[ak4 + 3][am] = av.w;
        }
        // ---- load B tile ----
        {
            int gn = blockIdx.x * BN + bn4;
            float4 bv = make_float4(0.f, 0.f, 0.f, 0.f);
            if (gn < N)  // N % 4 == 0 so whole float4 is in-bounds if gn < N
                bv = *(const float4*)(Bmat + (size_t)(k0 + bk) * N + gn);
            *(float4*)&Bs[bk][bn4] = bv;
        }
        __syncthreads();

        #pragma unroll
        for (int kk = 0; kk < BK; kk++) {
            float4 a = *(const float4*)&As[kk][ty * 4];
            float4 b = *(const float4*)&Bs[kk][tx * 4];
            float aa[4] = {a.x, a.y, a.z, a.w};
            float bb[4] = {b.x, b.y, b.z, b.w};
            #pragma unroll
            for (int i = 0; i < 4; i++)
                #pragma unroll
                for (int j = 0; j < 4; j++)
                    acc[i][j] = fmaf(aa[i], bb[j], acc[i][j]);
        }
        __syncthreads();
    }

    // ---- epilogue: add bias, store ----
    #pragma unroll
    for (int i = 0; i < 4; i++) {
        int m = row0 + i;
        #pragma unroll
        for (int j = 0; j < 4; j++) {
            int n = col0 + j;
            if (n < N)
                C[(size_t)m * N + n] = acc[i][j] + bias[n];
        }
    }
}

// ---------------- LayerNorm over last dim (512), in place -------------------
__global__ __launch_bounds__(128) void ln_kernel(
    float* __restrict__ h, const float* __restrict__ g, const float* __restrict__ b)
{
    int row = blockIdx.x;
    float4* hp = (float4*)(h + (size_t)row * LATENT);
    int t = threadIdx.x;              // 128 threads, 1 float4 each
    float4 v = hp[t];
    float s  = v.x + v.y + v.z + v.w;
    float sq = v.x * v.x + v.y * v.y + v.z * v.z + v.w * v.w;

    #pragma unroll
    for (int o = 16; o; o >>= 1) {
        s  += __shfl_xor_sync(0xffffffffu, s, o);
        sq += __shfl_xor_sync(0xffffffffu, sq, o);
    }
    __shared__ float rs[4], rq[4];
    int lane = t & 31, wid = t >> 5;
    if (lane == 0) { rs[wid] = s; rq[wid] = sq; }
    __syncthreads();
    float S  = rs[0] + rs[1] + rs[2] + rs[3];
    float SQ = rq[0] + rq[1] + rq[2] + rq[3];
    float mu  = S * (1.0f / LATENT);
    float var = SQ * (1.0f / LATENT) - mu * mu;
    float r = rsqrtf(var + 1e-5f);

    float4 gv = ((const float4*)g)[t];
    float4 bv = ((const float4*)b)[t];
    v.x = (v.x - mu) * r * gv.x + bv.x;
    v.y = (v.y - mu) * r * gv.y + bv.y;
    v.z = (v.z - mu) * r * gv.z + bv.z;
    v.w = (v.w - mu) * r * gv.w + bv.w;
    hp[t] = v;
}

// ---------------- Oja update: one block per (b,h) ---------------------------
// kvb row layout per b: H * 129; per head: [ks(64), vs(64), lr(1)]
__global__ __launch_bounds__(128) void oja_kernel(
    const float* __restrict__ kvb, const float* __restrict__ W, float* __restrict__ out)
{
    int bh = blockIdx.x;                       // b*8 + h
    const float* w = W   + (size_t)bh * (D * D);
    float*       o = out + (size_t)bh * (D * D);
    const float* kv = kvb + (size_t)(bh >> 3) * KVB_N + (size_t)(bh & 7) * (2 * D + 1);

    __shared__ float Ws[D * D];     // 16 KB
    __shared__ float vs[D], ksc[D], logit[D];
    __shared__ float lr_raw;

    int t = threadIdx.x;            // 128 threads

    #pragma unroll
    for (int i = t; i < (D * D) / 4; i += 128)
        ((float4*)Ws)[i] = ((const float4*)w)[i];
    if (t < D)     vs[t] = tanhf(kv[D + t]);
    if (t == 127)  lr_raw = kv[2 * D];
    __syncthreads();

    if (t < D) {
        float acc = 0.f;
        #pragma unroll 16
        for (int d = 0; d < D; d++)
            acc = fmaf(Ws[d * D + t], vs[d], acc);
        logit[t] = kv[t] - acc;
    }
    __syncthreads();

    // softmax over 64 (computed redundantly by all threads; cheap)
    float m = -1e30f;
    #pragma unroll
    for (int e = 0; e < D; e++) m = fmaxf(m, logit[e]);
    float ssum = 0.f;
    #pragma unroll
    for (int e = 0; e < D; e++) ssum += expf(logit[e] - m);
    float inv = 1.0f / ssum;
    float lr  = 1.0f / (1.0f + expf(-lr_raw));
    if (t < D) ksc[t] = expf(logit[t] - m) * inv * lr;
    __syncthreads();

    // out[d][e] = vs[d]*ksc[e] + W[d][e], vectorized
    #pragma unroll
    for (int i = t; i < (D * D) / 4; i += 128) {
        float4 wv = ((const float4*)Ws)[i];
        int d  = i >> 4;          // (i*4)/64
        int e0 = (i * 4) & (D - 1);
        float vd = vs[d];
        float4 r;
        r.x = fmaf(vd, ksc[e0 + 0], wv.x);
        r.y = fmaf(vd, ksc[e0 + 1], wv.y);
        r.z = fmaf(vd, ksc[e0 + 2], wv.z);
        r.w = fmaf(vd, ksc[e0 + 3], wv.w);
        ((float4*)o)[i] = r;
    }
}

// ---------------- launch ----------------------------------------------------
extern "C" void kernel_launch(void* const* d_in, const int* in_sizes, int n_in,
                              void* d_out, int out_size)
{
    const float* x     = (const float*)d_in[0];
    const float* z     = (const float*)d_in[1];
    const float* W     = (const float*)d_in[2];
    const float* ip_w  = (const float*)d_in[3];
    const float* ip_b  = (const float*)d_in[4];
    const float* ln_g  = (const float*)d_in[5];
    const float* ln_b  = (const float*)d_in[6];
    const float* mg_w  = (const float*)d_in[7];
    const float* mg_b  = (const float*)d_in[8];
    const float* kvb_w = (const float*)d_in[9];
    const float* kvb_b = (const float*)d_in[10];
    float* out = (float*)d_out;

    float *hP, *h2P, *kvbP;
    cudaGetSymbolAddress((void**)&hP,   g_h);
    cudaGetSymbolAddress((void**)&h2P,  g_h2);
    cudaGetSymbolAddress((void**)&kvbP, g_kvb);

    // GEMM1: h = x @ ip_w + ip_b   (M=4096, N=512, K=512)
    gemm_bias_kernel<false><<<dim3(512 / BN, B / BM), 256>>>(
        x, nullptr, ip_w, ip_b, hP, B, 512, 512);

    // LayerNorm in place
    ln_kernel<<<B, 128>>>(hP, ln_g, ln_b);

    // GEMM2: h2 = [h, z] @ mg_w + mg_b   (M=4096, N=512, K=1024)
    gemm_bias_kernel<true><<<dim3(512 / BN, B / BM), 256>>>(
        hP, z, mg_w, mg_b, h2P, B, 512, 1024);

    // GEMM3: kvb = h2 @ kvb_w + kvb_b   (M=4096, N=1032, K=512)
    gemm_bias_kernel<false><<<dim3((KVB_N + BN - 1) / BN, B / BM), 256>>>(
        h2P, nullptr, kvb_w, kvb_b, kvbP, B, KVB_N, 512);

    // Oja update: one block per (b, h)
    oja_kernel<<<B * H, 128>>>(kvbP, W, out);
}

// round 2
// speedup vs baseline: 1.1764x; 1.1764x over previous
#include <cuda_runtime.h>
#include <cuda_bf16.h>
#include <math.h>

// ---------------- scratch (no allocation allowed; use __device__ globals) ----
#define B 4096
#define LATENT 512
#define H 8
#define D 64
#define KVB_N (H * (2 * D + 1))   // 1032

__device__ float g_h[B * LATENT];      // post-GEMM1 / post-LN
__device__ float g_h2[B * LATENT];     // post-GEMM2
__device__ float g_kvb[B * KVB_N];     // post-GEMM3

// ---------------- GEMM: C[M,N] = A[M,K] @ Bmat[K,N] + bias ------------------
// CONCAT: A is concat([A0 (M,512), A1 (M,512)]) along K (K=1024)
// 128x64 block tile, BK=16, 256 threads, 8x4 per-thread micro-tile.
#define BM 128
#define BN 64
#define BK 16
#define TM 8
#define TN 4

template <bool CONCAT>
__global__ __launch_bounds__(256) void gemm_bias_kernel(
    const float* __restrict__ A0, const float* __restrict__ A1,
    const float* __restrict__ Bmat, const float* __restrict__ bias,
    float* __restrict__ C, int M, int N, int K)
{
    __shared__ float As[BK][BM];   // 8 KB
    __shared__ float Bs[BK][BN];   // 4 KB

    int t  = threadIdx.x;
    int tx = t & 15;               // 0..15 (N direction)
    int ty = t >> 4;               // 0..15 (M direction)
    int row0 = blockIdx.y * BM + ty * TM;
    int col0 = blockIdx.x * BN + tx * TN;

    // A-tile gmem load mapping: 128 rows, 2 float4 along K per thread
    int am = t >> 1;               // 0..127
    int ak = (t & 1) * 8;          // 0 or 8
    // B-tile gmem load mapping: 16 rows x 16 float4 (along N)
    int bk  = t >> 4;              // 0..15
    int bn4 = (t & 15) * 4;

    const int gmA = blockIdx.y * BM + am;
    const int gnB = blockIdx.x * BN + bn4;

    float acc[TM][TN] = {};
    float4 pa0, pa1, pb;

    // prefetch helpers -------------------------------------------------------
    auto loadA = [&](int k0) {
        int gk = k0 + ak;                    // gk..gk+7 on one side of 512 split
        const float* ap;
        if (CONCAT) {
            ap = (gk < 512) ? (A0 + (size_t)gmA * 512 + gk)
                            : (A1 + (size_t)gmA * 512 + (gk - 512));
        } else {
            ap = A0 + (size_t)gmA * K + gk;
        }
        pa0 = *(const float4*)ap;
        pa1 = *(const float4*)(ap + 4);
    };
    auto loadB = [&](int k0) {
        pb = make_float4(0.f, 0.f, 0.f, 0.f);
        if (gnB < N)
            pb = *(const float4*)(Bmat + (size_t)(k0 + bk) * N + gnB);
    };
    auto stage = [&]() {
        As[ak + 0][am] = pa0.x;  As[ak + 1][am] = pa0.y;
        As[ak + 2][am] = pa0.z;  As[ak + 3][am] = pa0.w;
        As[ak + 4][am] = pa1.x;  As[ak + 5][am] = pa1.y;
        As[ak + 6][am] = pa1.z;  As[ak + 7][am] = pa1.w;
        *(float4*)&Bs[bk][bn4] = pb;
    };

    loadA(0); loadB(0);

    for (int k0 = 0; k0 < K; k0 += BK) {
        stage();
        __syncthreads();
        if (k0 + BK < K) { loadA(k0 + BK); loadB(k0 + BK); }

        #pragma unroll
        for (int kk = 0; kk < BK; kk++) {
            float4 aA = *(const float4*)&As[kk][ty * TM];
            float4 aB = *(const float4*)&As[kk][ty * TM + 4];
            float4 bv = *(const float4*)&Bs[kk][tx * TN];
            float aa[TM] = {aA.x, aA.y, aA.z, aA.w, aB.x, aB.y, aB.z, aB.w};
            float bb[TN] = {bv.x, bv.y, bv.z, bv.w};
            #pragma unroll
            for (int i = 0; i < TM; i++)
                #pragma unroll
                for (int j = 0; j < TN; j++)
                    acc[i][j] = fmaf(aa[i], bb[j], acc[i][j]);
        }
        __syncthreads();
    }

    // ---- epilogue: add bias, vector store ----
    if (col0 < N) {                       // N % 4 == 0 so float4 fully in-bounds
        float4 bsv = *(const float4*)(bias + col0);
        #pragma unroll
        for (int i = 0; i < TM; i++) {
            float4 r;
            r.x = acc[i][0] + bsv.x;
            r.y = acc[i][1] + bsv.y;
            r.z = acc[i][2] + bsv.z;
            r.w = acc[i][3] + bsv.w;
            *(float4*)(C + (size_t)(row0 + i) * N + col0) = r;
        }
    }
}

// ---------------- LayerNorm over last dim (512), in place -------------------
__global__ __launch_bounds__(128) void ln_kernel(
    float* __restrict__ h, const float* __restrict__ g, const float* __restrict__ b)
{
    int row = blockIdx.x;
    float4* hp = (float4*)(h + (size_t)row * LATENT);
    int t = threadIdx.x;              // 128 threads, 1 float4 each
    float4 v = hp[t];
    float s  = v.x + v.y + v.z + v.w;
    float sq = v.x * v.x + v.y * v.y + v.z * v.z + v.w * v.w;

    #pragma unroll
    for (int o = 16; o; o >>= 1) {
        s  += __shfl_xor_sync(0xffffffffu, s, o);
        sq += __shfl_xor_sync(0xffffffffu, sq, o);
    }
    __shared__ float rs[4], rq[4];
    int lane = t & 31, wid = t >> 5;
    if (lane == 0) { rs[wid] = s; rq[wid] = sq; }
    __syncthreads();
    float S  = rs[0] + rs[1] + rs[2] + rs[3];
    float SQ = rq[0] + rq[1] + rq[2] + rq[3];
    float mu  = S * (1.0f / LATENT);
    float var = SQ * (1.0f / LATENT) - mu * mu;
    float r = rsqrtf(var + 1e-5f);

    float4 gv = ((const float4*)g)[t];
    float4 bv = ((const float4*)b)[t];
    v.x = (v.x - mu) * r * gv.x + bv.x;
    v.y = (v.y - mu) * r * gv.y + bv.y;
    v.z = (v.z - mu) * r * gv.z + bv.z;
    v.w = (v.w - mu) * r * gv.w + bv.w;
    hp[t] = v;
}

// ---------------- Oja update: one block per (b,h) ---------------------------
// kvb row layout per b: H * 129; per head: [ks(64), vs(64), lr(1)]
__global__ __launch_bounds__(128) void oja_kernel(
    const float* __restrict__ kvb, const float* __restrict__ W, float* __restrict__ out)
{
    int bh = blockIdx.x;                       // b*8 + h
    const float* w = W   + (size_t)bh * (D * D);
    float*       o = out + (size_t)bh * (D * D);
    const float* kv = kvb + (size_t)(bh >> 3) * KVB_N + (size_t)(bh & 7) * (2 * D + 1);

    __shared__ float Ws[D * D];     // 16 KB
    __shared__ float vs[D], ksc[D], logit[D];
    __shared__ float lr_raw;

    int t = threadIdx.x;            // 128 threads

    #pragma unroll
    for (int i = t; i < (D * D) / 4; i += 128)
        ((float4*)Ws)[i] = ((const float4*)w)[i];
    if (t < D)     vs[t] = tanhf(kv[D + t]);
    if (t == 127)  lr_raw = kv[2 * D];
    __syncthreads();

    if (t < D) {
        float acc = 0.f;
        #pragma unroll 16
        for (int d = 0; d < D; d++)
            acc = fmaf(Ws[d * D + t], vs[d], acc);
        logit[t] = kv[t] - acc;
    }
    __syncthreads();

    // softmax over 64 (computed redundantly by all threads; cheap)
    float m = -1e30f;
    #pragma unroll
    for (int e = 0; e < D; e++) m = fmaxf(m, logit[e]);
    float ssum = 0.f;
    #pragma unroll
    for (int e = 0; e < D; e++) ssum += expf(logit[e] - m);
    float inv = 1.0f / ssum;
    float lr  = 1.0f / (1.0f + expf(-lr_raw));
    if (t < D) ksc[t] = expf(logit[t] - m) * inv * lr;
    __syncthreads();

    // out[d][e] = vs[d]*ksc[e] + W[d][e], vectorized
    #pragma unroll
    for (int i = t; i < (D * D) / 4; i += 128) {
        float4 wv = ((const float4*)Ws)[i];
        int d  = i >> 4;          // (i*4)/64
        int e0 = (i * 4) & (D - 1);
        float vd = vs[d];
        float4 r;
        r.x = fmaf(vd, ksc[e0 + 0], wv.x);
        r.y = fmaf(vd, ksc[e0 + 1], wv.y);
        r.z = fmaf(vd, ksc[e0 + 2], wv.z);
        r.w = fmaf(vd, ksc[e0 + 3], wv.w);
        ((float4*)o)[i] = r;
    }
}

// ---------------- launch ----------------------------------------------------
extern "C" void kernel_launch(void* const* d_in, const int* in_sizes, int n_in,
                              void* d_out, int out_size)
{
    const float* x     = (const float*)d_in[0];
    const float* z     = (const float*)d_in[1];
    const float* W     = (const float*)d_in[2];
    const float* ip_w  = (const float*)d_in[3];
    const float* ip_b  = (const float*)d_in[4];
    const float* ln_g  = (const float*)d_in[5];
    const float* ln_b  = (const float*)d_in[6];
    const float* mg_w  = (const float*)d_in[7];
    const float* mg_b  = (const float*)d_in[8];
    const float* kvb_w = (const float*)d_in[9];
    const float* kvb_b = (const float*)d_in[10];
    float* out = (float*)d_out;

    float *hP, *h2P, *kvbP;
    cudaGetSymbolAddress((void**)&hP,   g_h);
    cudaGetSymbolAddress((void**)&h2P,  g_h2);
    cudaGetSymbolAddress((void**)&kvbP, g_kvb);

    // GEMM1: h = x @ ip_w + ip_b   (M=4096, N=512, K=512)
    gemm_bias_kernel<false><<<dim3(512 / BN, B / BM), 256>>>(
        x, nullptr, ip_w, ip_b, hP, B, 512, 512);

    // LayerNorm in place
    ln_kernel<<<B, 128>>>(hP, ln_g, ln_b);

    // GEMM2: h2 = [h, z] @ mg_w + mg_b   (M=4096, N=512, K=1024)
    gemm_bias_kernel<true><<<dim3(512 / BN, B / BM), 256>>>(
        hP, z, mg_w, mg_b, h2P, B, 512, 1024);

    // GEMM3: kvb = h2 @ kvb_w + kvb_b   (M=4096, N=1032, K=512)
    gemm_bias_kernel<false><<<dim3((KVB_N + BN - 1) / BN, B / BM), 256>>>(
        h2P, nullptr, kvb_w, kvb_b, kvbP, B, KVB_N, 512);

    // Oja update: one block per (b, h)
    oja_kernel<<<B * H, 128>>>(kvbP, W, out);
}